// round 10
// baseline (speedup 1.0000x reference)
#include <cuda_runtime.h>
#include <cuda_bf16.h>

// RippleNet: H=2, B=2048, M=64, D=16, N_ENT=500000, N_REL=32
// inputs: items[B] i32, heads[H,B,M] i32, relations[H,B,M] i32,
//         tails[H,B,M] i32, ent_emb[N_ENT,16] f32, rel_emb[32,16,16] f32
// output: predicts[B] f32

#define H_ 2
#define B_ 2048
#define M_ 64
#define D_ 16
#define NREL_ 32
#define QS 20   // q row stride in floats: float4-aligned, low bank conflict

// One block per b, 128 threads (proven best latency structure).
// Gathers: quad (4 lanes) = one 64B entity row; thread (quad,ch) owns rows
// {quad, quad+32, quad+64, quad+96}, 16B chunk ch.
// q-phase: octet (8 lanes) = one rel; each instr touches one full 128B line.
// Pipeline: head gathers -> q rel#1 -> tail gathers -> q rel#2 -> dots
// (halves front-batch MLP_p1 to cut cross-CTA L1tex queue spread).
__global__ __launch_bounds__(128, 8) void ripple_kernel(
    const int* __restrict__ items,
    const int* __restrict__ heads,
    const int* __restrict__ rels,
    const int* __restrict__ tails,
    const float* __restrict__ ent,
    const float* __restrict__ rel,
    float* __restrict__ out)
{
    const int b    = blockIdx.x;
    const int tid  = threadIdx.x;
    const int quad = tid >> 2;
    const int ch   = tid & 3;
    const int j0   = ch * 4;

    __shared__ float  item_s[D_];
    __shared__ int    idxh_s[128], idxr_s[128], idxt_s[128];
    __shared__ float  q[NREL_ * QS];
    __shared__ float4 wsum[4];        // per-warp {se0, ses0, se1, ses1}

    // ---- coalesced index staging: 3 LDG.32/thread, 1 wf/instr/warp ----
    {
        const int base = (tid >> 6) * (B_ * M_) + b * M_ + (tid & 63);
        idxh_s[tid] = __ldg(heads + base);
        idxr_s[tid] = __ldg(rels  + base);
        idxt_s[tid] = __ldg(tails + base);
    }
    const int it = items[b];
    if (tid < D_) item_s[tid] = __ldg(ent + (size_t)it * D_ + tid);
    __syncthreads();

    // q-phase octet decomposition
    const int lane = tid & 31;
    const int O    = (tid >> 5) * 4 + ((lane >> 3) & 3);   // octet 0..15
    const int half = (lane >> 2) & 1;

    // ---- batch 1: head gathers + item chunk ----
    int hidx[4], ridx[4], tidx[4];
    #pragma unroll
    for (int k = 0; k < 4; k++) {
        const int row = quad + 32 * k;
        hidx[k] = idxh_s[row];
        ridx[k] = idxr_s[row];
        tidx[k] = idxt_s[row];
    }
    const float4 vi = __ldg((const float4*)(ent + (size_t)it * D_ + j0));
    float4 hv[4];
    #pragma unroll
    for (int k = 0; k < 4; k++)
        hv[k] = __ldg((const float4*)(ent + (size_t)hidx[k] * D_ + j0));

    // ---- q rel #1 (overlaps head-gather latency) ----
    {
        const int r = O;
        const float4* Rp = (const float4*)(rel + r * (D_ * D_)) + ch;
        float4 acc = make_float4(0.f, 0.f, 0.f, 0.f);
        #pragma unroll
        for (int k = 0; k < 8; k++) {
            const int i = 2 * k + half;
            const float4 rv = Rp[i * 4];
            const float  wi = item_s[i];
            acc.x = fmaf(wi, rv.x, acc.x);
            acc.y = fmaf(wi, rv.y, acc.y);
            acc.z = fmaf(wi, rv.z, acc.z);
            acc.w = fmaf(wi, rv.w, acc.w);
        }
        acc.x += __shfl_xor_sync(0xffffffffu, acc.x, 4);
        acc.y += __shfl_xor_sync(0xffffffffu, acc.y, 4);
        acc.z += __shfl_xor_sync(0xffffffffu, acc.z, 4);
        acc.w += __shfl_xor_sync(0xffffffffu, acc.w, 4);
        if (half == 0)
            *(float4*)&q[r * QS + j0] = acc;
    }

    // ---- batch 2: tail gathers ----
    float4 tv[4];
    #pragma unroll
    for (int k = 0; k < 4; k++)
        tv[k] = __ldg((const float4*)(ent + (size_t)tidx[k] * D_ + j0));

    // ---- q rel #2 (overlaps tail-gather latency) ----
    {
        const int r = O + 16;
        const float4* Rp = (const float4*)(rel + r * (D_ * D_)) + ch;
        float4 acc = make_float4(0.f, 0.f, 0.f, 0.f);
        #pragma unroll
        for (int k = 0; k < 8; k++) {
            const int i = 2 * k + half;
            const float4 rv = Rp[i * 4];
            const float  wi = item_s[i];
            acc.x = fmaf(wi, rv.x, acc.x);
            acc.y = fmaf(wi, rv.y, acc.y);
            acc.z = fmaf(wi, rv.z, acc.z);
            acc.w = fmaf(wi, rv.w, acc.w);
        }
        acc.x += __shfl_xor_sync(0xffffffffu, acc.x, 4);
        acc.y += __shfl_xor_sync(0xffffffffu, acc.y, 4);
        acc.z += __shfl_xor_sync(0xffffffffu, acc.z, 4);
        acc.w += __shfl_xor_sync(0xffffffffu, acc.w, 4);
        if (half == 0)
            *(float4*)&q[r * QS + j0] = acc;
    }

    // ---- tail dots (tv dies here) ----
    float s[4];
    #pragma unroll
    for (int k = 0; k < 4; k++) {
        float ps = fmaf(vi.x, tv[k].x, fmaf(vi.y, tv[k].y,
                   fmaf(vi.z, tv[k].z, vi.w * tv[k].w)));
        ps += __shfl_xor_sync(0xffffffffu, ps, 1);
        ps += __shfl_xor_sync(0xffffffffu, ps, 2);
        s[k] = ps;
    }

    __syncthreads();   // q ready

    // ---- head dots: logit via q[ridx] (LDS.128) ----
    float l[4];
    #pragma unroll
    for (int k = 0; k < 4; k++) {
        const float4 w = *(const float4*)&q[ridx[k] * QS + j0];
        float p = fmaf(w.x, hv[k].x, fmaf(w.y, hv[k].y,
                  fmaf(w.z, hv[k].z, w.w * hv[k].w)));
        p += __shfl_xor_sync(0xffffffffu, p, 1);
        p += __shfl_xor_sync(0xffffffffu, p, 2);
        l[k] = p;
    }

    // ---- softmax w/o max subtraction (|l| ~ 0.1; exp safe, identical math) ----
    const float e0 = __expf(l[0]), e1 = __expf(l[1]);
    const float e2 = __expf(l[2]), e3 = __expf(l[3]);
    float se0  = e0 + e1;
    float ses0 = fmaf(e0, s[0], e1 * s[1]);
    float se1  = e2 + e3;
    float ses1 = fmaf(e2, s[2], e3 * s[3]);

    // lanes within a quad hold identical values -> reduce offsets 16,8,4 only
    #pragma unroll
    for (int off = 16; off >= 4; off >>= 1) {
        se0  += __shfl_xor_sync(0xffffffffu, se0,  off);
        ses0 += __shfl_xor_sync(0xffffffffu, ses0, off);
        se1  += __shfl_xor_sync(0xffffffffu, se1,  off);
        ses1 += __shfl_xor_sync(0xffffffffu, ses1, off);
    }
    if ((tid & 31) == 0)
        wsum[tid >> 5] = make_float4(se0, ses0, se1, ses1);
    __syncthreads();

    if (tid == 0) {
        float SE0 = 0.f, SES0 = 0.f, SE1 = 0.f, SES1 = 0.f;
        #pragma unroll
        for (int i = 0; i < 4; i++) {
            const float4 v = wsum[i];
            SE0 += v.x; SES0 += v.y; SE1 += v.z; SES1 += v.w;
        }
        // 4x quad-lane replication cancels in each ratio
        const float x = SES0 / SE0 + SES1 / SE1;
        out[b] = 1.f / (1.f + __expf(-x));
    }
}

extern "C" void kernel_launch(void* const* d_in, const int* in_sizes, int n_in,
                              void* d_out, int out_size) {
    const int*   items = (const int*)  d_in[0];
    const int*   heads = (const int*)  d_in[1];
    const int*   rels  = (const int*)  d_in[2];
    const int*   tails = (const int*)  d_in[3];
    const float* ent   = (const float*)d_in[4];
    const float* rel   = (const float*)d_in[5];
    float* out = (float*)d_out;

    ripple_kernel<<<B_, 128>>>(items, heads, rels, tails, ent, rel, out);
}

// round 11
// speedup vs baseline: 1.0226x; 1.0226x over previous
#include <cuda_runtime.h>
#include <cuda_bf16.h>

// RippleNet: H=2, B=2048, M=64, D=16, N_ENT=500000, N_REL=32
// inputs: items[B] i32, heads[H,B,M] i32, relations[H,B,M] i32,
//         tails[H,B,M] i32, ent_emb[N_ENT,16] f32, rel_emb[32,16,16] f32
// output: predicts[B] f32

#define H_ 2
#define B_ 2048
#define M_ 64
#define D_ 16
#define NREL_ 32
#define QS 20   // q row stride in floats: float4-aligned, low bank conflict

// One CTA handles TWO items: b0 = blockIdx.x, b1 = b0 + 1024. Grid 1024 at
// 8 CTA/SM -> single wave (no wave-quantization tail). 128 threads, R9 map:
// quad (4 lanes) = one 64B entity row, thread owns rows {quad,+32,+64,+96},
// chunk ch. Octet q-phase computes BOTH items' q from the same rel loads.
__global__ __launch_bounds__(128, 8) void ripple_kernel(
    const int* __restrict__ items,
    const int* __restrict__ heads,
    const int* __restrict__ rels,
    const int* __restrict__ tails,
    const float* __restrict__ ent,
    const float* __restrict__ rel,
    float* __restrict__ out)
{
    const int b0   = blockIdx.x;          // second item: b0 + 1024
    const int tid  = threadIdx.x;
    const int quad = tid >> 2;
    const int ch   = tid & 3;
    const int j0   = ch * 4;

    __shared__ float  item_s[2][D_];
    __shared__ int    idx_s[3][2][128];   // [head|rel|tail][b][row]
    __shared__ float  q[2][NREL_ * QS];
    __shared__ float4 wsum[4];

    // ---- stage all indices for both b's (6 coalesced LDG.32/thread) ----
    {
        const int hop = tid >> 6, m = tid & 63;
        #pragma unroll
        for (int a = 0; a < 3; a++) {
            const int* src = (a == 0 ? heads : (a == 1 ? rels : tails));
            idx_s[a][0][tid] = __ldg(src + hop * (B_ * M_) + b0 * M_ + m);
            idx_s[a][1][tid] = __ldg(src + hop * (B_ * M_) + (b0 + 1024) * M_ + m);
        }
    }
    if (tid < 32) {
        const int bb = tid >> 4, j = tid & 15;
        item_s[bb][j] = __ldg(ent + (size_t)__ldg(items + b0 + bb * 1024) * D_ + j);
    }
    __syncthreads();

    // ---- b0 gathers: full front-batch (8 LDG.128, quad-coalesced) ----
    int hidx0[4], ridx0[4], tidx0[4];
    #pragma unroll
    for (int k = 0; k < 4; k++) {
        const int row = quad + 32 * k;
        hidx0[k] = idx_s[0][0][row];
        ridx0[k] = idx_s[1][0][row];
        tidx0[k] = idx_s[2][0][row];
    }
    float4 hv[4], tv[4];
    #pragma unroll
    for (int k = 0; k < 4; k++)
        hv[k] = __ldg((const float4*)(ent + (size_t)hidx0[k] * D_ + j0));
    #pragma unroll
    for (int k = 0; k < 4; k++)
        tv[k] = __ldg((const float4*)(ent + (size_t)tidx0[k] * D_ + j0));
    const float4 vi0 = *(const float4*)&item_s[0][j0];
    const float4 vi1 = *(const float4*)&item_s[1][j0];

    // ---- dual q-phase: octet (8 lanes) = one rel; rows 2k+half = one 128B
    //      line per step; SAME rel loads feed both items' accumulators ----
    {
        const int lane = tid & 31;
        const int O    = (tid >> 5) * 4 + ((lane >> 3) & 3);   // octet 0..15
        const int half = (lane >> 2) & 1;
        #pragma unroll
        for (int rr = 0; rr < 2; rr++) {
            const int r = O + 16 * rr;
            const float4* Rp = (const float4*)(rel + r * (D_ * D_)) + ch;
            float4 a0 = make_float4(0.f, 0.f, 0.f, 0.f);
            float4 a1 = make_float4(0.f, 0.f, 0.f, 0.f);
            #pragma unroll
            for (int k = 0; k < 8; k++) {
                const int i = 2 * k + half;
                const float4 rv = Rp[i * 4];
                const float w0 = item_s[0][i];
                const float w1 = item_s[1][i];
                a0.x = fmaf(w0, rv.x, a0.x); a0.y = fmaf(w0, rv.y, a0.y);
                a0.z = fmaf(w0, rv.z, a0.z); a0.w = fmaf(w0, rv.w, a0.w);
                a1.x = fmaf(w1, rv.x, a1.x); a1.y = fmaf(w1, rv.y, a1.y);
                a1.z = fmaf(w1, rv.z, a1.z); a1.w = fmaf(w1, rv.w, a1.w);
            }
            a0.x += __shfl_xor_sync(0xffffffffu, a0.x, 4);
            a0.y += __shfl_xor_sync(0xffffffffu, a0.y, 4);
            a0.z += __shfl_xor_sync(0xffffffffu, a0.z, 4);
            a0.w += __shfl_xor_sync(0xffffffffu, a0.w, 4);
            a1.x += __shfl_xor_sync(0xffffffffu, a1.x, 4);
            a1.y += __shfl_xor_sync(0xffffffffu, a1.y, 4);
            a1.z += __shfl_xor_sync(0xffffffffu, a1.z, 4);
            a1.w += __shfl_xor_sync(0xffffffffu, a1.w, 4);
            if (half == 0) {
                *(float4*)&q[0][r * QS + j0] = a0;
                *(float4*)&q[1][r * QS + j0] = a1;
            }
        }
    }

    // ---- b0 tail dots (tv dies) ----
    float s[4];
    #pragma unroll
    for (int k = 0; k < 4; k++) {
        float ps = fmaf(vi0.x, tv[k].x, fmaf(vi0.y, tv[k].y,
                   fmaf(vi0.z, tv[k].z, vi0.w * tv[k].w)));
        ps += __shfl_xor_sync(0xffffffffu, ps, 1);
        ps += __shfl_xor_sync(0xffffffffu, ps, 2);
        s[k] = ps;
    }

    // ---- issue b1 tail gathers (tv regs free now; fly across the barrier) ----
    int ridx1[4];
    #pragma unroll
    for (int k = 0; k < 4; k++) {
        const int row = quad + 32 * k;
        tv[k]   = __ldg((const float4*)(ent + (size_t)idx_s[2][1][row] * D_ + j0));
        ridx1[k] = idx_s[1][1][row];
    }

    __syncthreads();   // q ready

    // ---- b0 head dots (hv dies) ----
    float l[4];
    #pragma unroll
    for (int k = 0; k < 4; k++) {
        const float4 w = *(const float4*)&q[0][ridx0[k] * QS + j0];
        float p = fmaf(w.x, hv[k].x, fmaf(w.y, hv[k].y,
                  fmaf(w.z, hv[k].z, w.w * hv[k].w)));
        p += __shfl_xor_sync(0xffffffffu, p, 1);
        p += __shfl_xor_sync(0xffffffffu, p, 2);
        l[k] = p;
    }

    // ---- issue b1 head gathers (hv regs free; overlap with b0 softmax) ----
    #pragma unroll
    for (int k = 0; k < 4; k++) {
        const int row = quad + 32 * k;
        hv[k] = __ldg((const float4*)(ent + (size_t)idx_s[0][1][row] * D_ + j0));
    }

    // ---- b0 softmax (no max subtraction: |l| ~ 0.1, exp safe) ----
    {
        const float e0 = __expf(l[0]), e1 = __expf(l[1]);
        const float e2 = __expf(l[2]), e3 = __expf(l[3]);
        float se0  = e0 + e1,  ses0 = fmaf(e0, s[0], e1 * s[1]);
        float se1  = e2 + e3,  ses1 = fmaf(e2, s[2], e3 * s[3]);
        #pragma unroll
        for (int off = 16; off >= 4; off >>= 1) {
            se0  += __shfl_xor_sync(0xffffffffu, se0,  off);
            ses0 += __shfl_xor_sync(0xffffffffu, ses0, off);
            se1  += __shfl_xor_sync(0xffffffffu, se1,  off);
            ses1 += __shfl_xor_sync(0xffffffffu, ses1, off);
        }
        if ((tid & 31) == 0)
            wsum[tid >> 5] = make_float4(se0, ses0, se1, ses1);
    }
    __syncthreads();
    if (tid == 0) {
        float SE0 = 0.f, SES0 = 0.f, SE1 = 0.f, SES1 = 0.f;
        #pragma unroll
        for (int i = 0; i < 4; i++) {
            const float4 v = wsum[i];
            SE0 += v.x; SES0 += v.y; SE1 += v.z; SES1 += v.w;
        }
        const float x = SES0 / SE0 + SES1 / SE1;
        out[b0] = 1.f / (1.f + __expf(-x));
    }
    __syncthreads();   // wsum reusable

    // ---- b1 tail dots ----
    #pragma unroll
    for (int k = 0; k < 4; k++) {
        float ps = fmaf(vi1.x, tv[k].x, fmaf(vi1.y, tv[k].y,
                   fmaf(vi1.z, tv[k].z, vi1.w * tv[k].w)));
        ps += __shfl_xor_sync(0xffffffffu, ps, 1);
        ps += __shfl_xor_sync(0xffffffffu, ps, 2);
        s[k] = ps;
    }
    // ---- b1 head dots ----
    #pragma unroll
    for (int k = 0; k < 4; k++) {
        const float4 w = *(const float4*)&q[1][ridx1[k] * QS + j0];
        float p = fmaf(w.x, hv[k].x, fmaf(w.y, hv[k].y,
                  fmaf(w.z, hv[k].z, w.w * hv[k].w)));
        p += __shfl_xor_sync(0xffffffffu, p, 1);
        p += __shfl_xor_sync(0xffffffffu, p, 2);
        l[k] = p;
    }
    // ---- b1 softmax ----
    {
        const float e0 = __expf(l[0]), e1 = __expf(l[1]);
        const float e2 = __expf(l[2]), e3 = __expf(l[3]);
        float se0  = e0 + e1,  ses0 = fmaf(e0, s[0], e1 * s[1]);
        float se1  = e2 + e3,  ses1 = fmaf(e2, s[2], e3 * s[3]);
        #pragma unroll
        for (int off = 16; off >= 4; off >>= 1) {
            se0  += __shfl_xor_sync(0xffffffffu, se0,  off);
            ses0 += __shfl_xor_sync(0xffffffffu, ses0, off);
            se1  += __shfl_xor_sync(0xffffffffu, se1,  off);
            ses1 += __shfl_xor_sync(0xffffffffu, ses1, off);
        }
        if ((tid & 31) == 0)
            wsum[tid >> 5] = make_float4(se0, ses0, se1, ses1);
    }
    __syncthreads();
    if (tid == 0) {
        float SE0 = 0.f, SES0 = 0.f, SE1 = 0.f, SES1 = 0.f;
        #pragma unroll
        for (int i = 0; i < 4; i++) {
            const float4 v = wsum[i];
            SE0 += v.x; SES0 += v.y; SE1 += v.z; SES1 += v.w;
        }
        const float x = SES0 / SE0 + SES1 / SE1;
        out[b0 + 1024] = 1.f / (1.f + __expf(-x));
    }
}

extern "C" void kernel_launch(void* const* d_in, const int* in_sizes, int n_in,
                              void* d_out, int out_size) {
    const int*   items = (const int*)  d_in[0];
    const int*   heads = (const int*)  d_in[1];
    const int*   rels  = (const int*)  d_in[2];
    const int*   tails = (const int*)  d_in[3];
    const float* ent   = (const float*)d_in[4];
    const float* rel   = (const float*)d_in[5];
    float* out = (float*)d_out;

    ripple_kernel<<<B_ / 2, 128>>>(items, heads, rels, tails, ent, rel, out);
}